// round 14
// baseline (speedup 1.0000x reference)
#include <cuda_runtime.h>
#include <cuda_fp16.h>
#include <math.h>
#include <stdint.h>

#define B    64
#define T    2048
#define D    128
#define H    256
#define G4   1024
#define OUTN 64
#define MROWS (T * B)
#define NB_L0 32
#define NB_L1 32
#define NBLK  (NB_L0 + NB_L1)
#define RING 4
#define ARR  8          // block arrivals per counter (32 blocks / 4 bg)

typedef unsigned long long ull;

// lstm dynamic SMEM (bytes): A 128x520x2=133120 | B 16x520x2=16640 | red 128x17x4=8704
#define OFF_B   133120
#define OFF_RED 149760
#define SMEM_BYTES 158720

// ---------------- scratch ------------------------------------------------------
__device__ __half g_eh[(size_t)MROWS * D];          // [m][d] fp16
__device__ float  g_xg0[(size_t)MROWS * G4];        // [m][col] (includes bias0)
__device__ __half g_h1all[(size_t)MROWS * H];       // [m][k] fp16
__device__ float  g_logits[(size_t)MROWS * OUTN];
__device__ __half g_h0buf[RING][B * H];             // [ring][b][k]
__device__ __half g_h1buf[RING][B * H];
__device__ float  g_bias0[G4];
__device__ float  g_bias1[G4];
__device__ int    g_done0q[T][4];
__device__ int    g_done1q[T][4];

__device__ __forceinline__ float tanha(float x) {
    float r;
    asm("tanh.approx.f32 %0, %1;" : "=f"(r) : "f"(x));
    return r;
}
__device__ __forceinline__ float sigf(float x) { return 0.5f * tanha(0.5f * x) + 0.5f; }

__device__ __forceinline__ void waitq(const int* p, int thr) {
    int v;
    do {
        asm volatile("ld.global.acquire.gpu.b32 %0, [%1];" : "=r"(v) : "l"(p) : "memory");
    } while (v < thr);
}
__device__ __forceinline__ void arrive_rel(int* p) {
    asm volatile("red.release.gpu.global.add.u32 [%0], %1;" :: "l"(p), "r"(1) : "memory");
}

// ---------------- warp MMA helpers -----------------------------------------------
__device__ __forceinline__ uint32_t smem_u32(const void* p) {
    uint32_t a;
    asm("{ .reg .u64 t; cvta.to.shared.u64 t, %1; cvt.u32.u64 %0, t; }" : "=r"(a) : "l"(p));
    return a;
}
__device__ __forceinline__ void ldsm_x4(uint32_t& a0, uint32_t& a1, uint32_t& a2,
                                        uint32_t& a3, uint32_t addr) {
    asm volatile("ldmatrix.sync.aligned.m8n8.x4.shared.b16 {%0,%1,%2,%3}, [%4];"
                 : "=r"(a0), "=r"(a1), "=r"(a2), "=r"(a3) : "r"(addr));
}
__device__ __forceinline__ void ldsm_x2(uint32_t& b0, uint32_t& b1, uint32_t addr) {
    asm volatile("ldmatrix.sync.aligned.m8n8.x2.shared.b16 {%0,%1}, [%2];"
                 : "=r"(b0), "=r"(b1) : "r"(addr));
}
__device__ __forceinline__ void mma16816(float* d, uint32_t a0, uint32_t a1,
                                         uint32_t a2, uint32_t a3,
                                         uint32_t b0, uint32_t b1) {
    asm volatile(
        "mma.sync.aligned.m16n8k16.row.col.f32.f16.f16.f32 "
        "{%0,%1,%2,%3}, {%4,%5,%6,%7}, {%8,%9}, {%0,%1,%2,%3};"
        : "+f"(d[0]), "+f"(d[1]), "+f"(d[2]), "+f"(d[3])
        : "r"(a0), "r"(a1), "r"(a2), "r"(a3), "r"(b0), "r"(b1));
}

// ---------------- tiny kernels -----------------------------------------------------
__global__ void prep_bias(const float* __restrict__ bih0, const float* __restrict__ bhh0,
                          const float* __restrict__ bih1, const float* __restrict__ bhh1) {
    int i = blockIdx.x * 256 + threadIdx.x;
    if (i < G4) {
        g_bias0[i] = bih0[i] + bhh0[i];
        g_bias1[i] = bih1[i] + bhh1[i];
    }
}

__global__ void embed_kernel(const int* __restrict__ x, const float* __restrict__ table) {
    size_t idx = ((size_t)blockIdx.x * 256 + threadIdx.x) * 2;
    int d = (int)(idx & (D - 1));
    size_t m = idx >> 7;
    int t = (int)(m >> 6);
    int b = (int)(m & 63);
    int xi = __ldg(&x[(size_t)b * T + t]);
    __half2 v;
    if (xi == 0) {
        v = __floats2half2_rn(0.f, 0.f);
    } else {
        const float* src = &table[(size_t)xi * D + d];
        v = __floats2half2_rn(src[0], src[1]);
    }
    *(__half2*)&g_eh[idx] = v;
}

// ------- xg0 = e @ Wih0^T + bias0 via HMMA; M=131072, N(gates)=1024, K=128 ---------
#define XS 72
__global__ void __launch_bounds__(256, 2) gemm_xg0(const float* __restrict__ Wih) {
    __shared__ __half As[128 * XS];
    __shared__ __half Bs[64 * XS];
    const int tid = threadIdx.x;
    const int warp = tid >> 5, lane = tid & 31;
    const size_t m0 = (size_t)blockIdx.y * 128;
    const int    n0 = blockIdx.x * 64;

    const int wm = (warp & 3) * 32;
    const int wn = (warp >> 2) * 32;

    float d[2][4][4];
#pragma unroll
    for (int mt = 0; mt < 2; mt++)
#pragma unroll
        for (int nt = 0; nt < 4; nt++)
#pragma unroll
            for (int i = 0; i < 4; i++) d[mt][nt][i] = 0.f;

    const uint32_t sA = smem_u32(As), sB = smem_u32(Bs);
    const uint32_t aA0 = sA + 2u * (uint32_t)((wm + (lane & 15)) * XS + ((lane >> 4) << 3));
    const uint32_t aA1 = aA0 + 2u * 16 * XS;
    const uint32_t aB0 = sB + 2u * (uint32_t)((wn + (lane & 7) + ((lane >> 4) << 3)) * XS
                                              + (((lane >> 3) & 1) << 3));
    const uint32_t aB1 = aB0 + 2u * 16 * XS;

    for (int kc = 0; kc < 2; kc++) {
        for (int i = tid; i < 128 * 8; i += 256) {
            int r = i >> 3, u = i & 7;
            *(uint4*)&As[r * XS + u * 8] =
                *(const uint4*)&g_eh[(m0 + r) * D + kc * 64 + u * 8];
        }
        for (int i = tid; i < 1024; i += 256) {
            int r = i >> 4, u = i & 15;
            float4 w = *(const float4*)&Wih[(size_t)(n0 + r) * D + kc * 64 + u * 4];
            __half2* dst = (__half2*)&Bs[r * XS + u * 4];
            dst[0] = __floats2half2_rn(w.x, w.y);
            dst[1] = __floats2half2_rn(w.z, w.w);
        }
        __syncthreads();
#pragma unroll
        for (int kk = 0; kk < 4; kk++) {
            uint32_t a0[4], a1[4], b0[4], b1[4];
            ldsm_x4(a0[0], a0[1], a0[2], a0[3], aA0 + kk * 32);
            ldsm_x4(a1[0], a1[1], a1[2], a1[3], aA1 + kk * 32);
            ldsm_x4(b0[0], b0[1], b0[2], b0[3], aB0 + kk * 32);
            ldsm_x4(b1[0], b1[1], b1[2], b1[3], aB1 + kk * 32);
#pragma unroll
            for (int nt = 0; nt < 2; nt++) {
                mma16816(d[0][nt],     a0[0], a0[1], a0[2], a0[3], b0[nt * 2], b0[nt * 2 + 1]);
                mma16816(d[1][nt],     a1[0], a1[1], a1[2], a1[3], b0[nt * 2], b0[nt * 2 + 1]);
                mma16816(d[0][nt + 2], a0[0], a0[1], a0[2], a0[3], b1[nt * 2], b1[nt * 2 + 1]);
                mma16816(d[1][nt + 2], a1[0], a1[1], a1[2], a1[3], b1[nt * 2], b1[nt * 2 + 1]);
            }
        }
        __syncthreads();
    }
    const int rowq = lane >> 2, c2 = (lane & 3) * 2;
#pragma unroll
    for (int mt = 0; mt < 2; mt++) {
#pragma unroll
        for (int nt = 0; nt < 4; nt++) {
            int gc = n0 + wn + nt * 8 + c2;
            float bv0 = g_bias0[gc], bv1 = g_bias0[gc + 1];
            size_t gr = m0 + wm + mt * 16 + rowq;
            float2 v0 = make_float2(d[mt][nt][0] + bv0, d[mt][nt][1] + bv1);
            float2 v1 = make_float2(d[mt][nt][2] + bv0, d[mt][nt][3] + bv1);
            *(float2*)&g_xg0[gr * G4 + gc]       = v0;
            *(float2*)&g_xg0[(gr + 8) * G4 + gc] = v1;
        }
    }
}

// ---------------- persistent HMMA 2-layer LSTM --------------------------------------
// Block tile: 32 j x 16 b -> M=128 gate rows (r = g*32+jj), N=16, K=256/512.
extern __shared__ __align__(1024) char smem_raw[];

__global__ void __launch_bounds__(256, 1) lstm_kernel(
    const float* __restrict__ Whh0,
    const float* __restrict__ Wih1,
    const float* __restrict__ Whh1)
{
    float* red = (float*)(smem_raw + OFF_RED);   // [128][17]
    const uint32_t sbase = smem_u32(smem_raw);
    const int bid = blockIdx.x, tid = threadIdx.x;
    const int warp = tid >> 5, lane = tid & 31;

    const bool isL0 = bid < NB_L0;
    const int lb = isL0 ? bid : bid - NB_L0;
    const int jg = lb >> 2, bg = lb & 3;
    const int j0 = jg * 32, b0 = bg * 16;
    const int K  = isL0 ? 256 : 512;
    const int SA = isL0 ? 264 : 520;

    // ---- weights fp16 -> SMEM (rows r = g*32+jj) ----
    {
        __half* A_s = (__half*)smem_raw;
        for (int i = tid; i < 128 * K; i += 256) {
            int r = i / K, k = i - r * K;
            int grow = (r >> 5) * 256 + j0 + (r & 31);
            float w;
            if (isL0)          w = Whh0[(size_t)grow * H + k];
            else if (k < 256)  w = Wih1[(size_t)grow * H + k];
            else               w = Whh1[(size_t)grow * H + (k - 256)];
            A_s[r * SA + k] = __float2half_rn(w);
        }
    }

    // warp m-tile: rows r0 = warp*16; B x4 covers both n-groups (16 b)
    const int r0 = warp * 16;
    const uint32_t aA = sbase + 2u * (uint32_t)((r0 + (lane & 15)) * SA + ((lane >> 4) << 3));
    const uint32_t aB = sbase + OFF_B +
        2u * (uint32_t)(((((lane >> 4) & 1) << 3) + (lane & 7)) * SA + (((lane >> 3) & 1) << 3));

    // activation: 512 (jj,bl) pairs, 2 per thread (bl and bl+8)
    const int jj = tid & 31, bl = tid >> 5;
    float c_reg[2] = {0.f, 0.f};
    float bi[4];
    if (!isL0) {
#pragma unroll
        for (int g = 0; g < 4; g++) bi[g] = g_bias1[g * 256 + j0 + jj];
    }
    __syncthreads();

    const uint32_t SBb = 2u * (uint32_t)SA;

    if (isL0) {
        // ===================== layer 0 =====================
        for (int t = 0; t < T; ++t) {
            float xp[4][2];
            {
#pragma unroll
                for (int half = 0; half < 2; half++) {
                    const float* xg = g_xg0 +
                        ((size_t)t * B + b0 + bl + half * 8) * G4 + j0 + jj;
#pragma unroll
                    for (int g = 0; g < 4; g++) xp[g][half] = xg[g * 256];
                }
            }

            if (t >= 1) {
                const int* pa = &g_done0q[t - 1][bg];
                const int* pb = &g_done1q[(t >= RING) ? (t - RING) : 0][bg];
                const bool needb = (t >= RING);
                int va, vb;
                do {
                    asm volatile("ld.global.acquire.gpu.b32 %0, [%1];"
                                 : "=r"(va) : "l"(pa) : "memory");
                    if (needb)
                        asm volatile("ld.global.acquire.gpu.b32 %0, [%1];"
                                     : "=r"(vb) : "l"(pb) : "memory");
                    else vb = ARR;
                } while (va < ARR || vb < ARR);
            }

            char* smB = smem_raw + OFF_B;
            const __half* hsrc = g_h0buf[(t + RING - 1) & (RING - 1)];
#pragma unroll
            for (int rep = 0; rep < 2; rep++) {
                int c = rep * 256 + tid;
                int n = c >> 5, u = c & 31;
                uint4 v = *(const uint4*)(hsrc + (size_t)(b0 + n) * 256 + u * 8);
                *(uint4*)(smB + n * SBb + u * 16) = v;
            }
            __syncthreads();

            float d0[4] = {0.f, 0.f, 0.f, 0.f};
            float d1[4] = {0.f, 0.f, 0.f, 0.f};
#pragma unroll 8
            for (int kk = 0; kk < 16; kk++) {
                uint32_t a0, a1, a2, a3, b0r, b1r, b2r, b3r;
                ldsm_x4(a0, a1, a2, a3, aA + kk * 32);
                ldsm_x4(b0r, b1r, b2r, b3r, aB + kk * 32);
                mma16816(d0, a0, a1, a2, a3, b0r, b1r);
                mma16816(d1, a0, a1, a2, a3, b2r, b3r);
            }
            {
                int row = r0 + (lane >> 2);
                int col = (lane & 3) * 2;
                red[row * 17 + col]           = d0[0];
                red[row * 17 + col + 1]       = d0[1];
                red[(row + 8) * 17 + col]     = d0[2];
                red[(row + 8) * 17 + col + 1] = d0[3];
                red[row * 17 + col + 8]       = d1[0];
                red[row * 17 + col + 9]       = d1[1];
                red[(row + 8) * 17 + col + 8] = d1[2];
                red[(row + 8) * 17 + col + 9] = d1[3];
            }
            __syncthreads();

            {
#pragma unroll
                for (int half = 0; half < 2; half++) {
                    int blh = bl + half * 8;
                    float s0 = xp[0][half] + red[(jj)      * 17 + blh];
                    float s1 = xp[1][half] + red[(32 + jj) * 17 + blh];
                    float s2 = xp[2][half] + red[(64 + jj) * 17 + blh];
                    float s3 = xp[3][half] + red[(96 + jj) * 17 + blh];
                    c_reg[half] = sigf(s1) * c_reg[half] + sigf(s0) * tanha(s2);
                    float hval = sigf(s3) * tanha(c_reg[half]);
                    g_h0buf[t & (RING - 1)][(size_t)(b0 + blh) * 256 + j0 + jj] =
                        __float2half_rn(hval);
                }
            }
            __syncthreads();
            if (tid == 0) arrive_rel(&g_done0q[t][bg]);
        }
    } else {
        // ===================== layer 1 (h0 phase first) =====================
        for (int tp = 0; tp < T; ++tp) {
            char* smB = smem_raw + OFF_B;

            waitq(&g_done0q[tp][bg], ARR);
            {
                const __half* h0s = g_h0buf[tp & (RING - 1)];
#pragma unroll
                for (int rep = 0; rep < 2; rep++) {
                    int c = rep * 256 + tid;
                    int n = c >> 5, u = c & 31;
                    uint4 v = *(const uint4*)(h0s + (size_t)(b0 + n) * 256 + u * 8);
                    *(uint4*)(smB + n * SBb + u * 16) = v;
                }
            }
            __syncthreads();

            float d0[4] = {0.f, 0.f, 0.f, 0.f};
            float d1[4] = {0.f, 0.f, 0.f, 0.f};
#pragma unroll 8
            for (int kk = 0; kk < 16; kk++) {
                uint32_t a0, a1, a2, a3, b0r, b1r, b2r, b3r;
                ldsm_x4(a0, a1, a2, a3, aA + kk * 32);
                ldsm_x4(b0r, b1r, b2r, b3r, aB + kk * 32);
                mma16816(d0, a0, a1, a2, a3, b0r, b1r);
                mma16816(d1, a0, a1, a2, a3, b2r, b3r);
            }

            if (tp >= 1) waitq(&g_done1q[tp - 1][bg], ARR);
            {
                const __half* h1s = g_h1buf[(tp + RING - 1) & (RING - 1)];
#pragma unroll
                for (int rep = 0; rep < 2; rep++) {
                    int c = rep * 256 + tid;
                    int n = c >> 5, u = c & 31;
                    uint4 v = *(const uint4*)(h1s + (size_t)(b0 + n) * 256 + u * 8);
                    *(uint4*)(smB + n * SBb + 512 + u * 16) = v;
                }
            }
            __syncthreads();

#pragma unroll 8
            for (int kk = 16; kk < 32; kk++) {
                uint32_t a0, a1, a2, a3, b0r, b1r, b2r, b3r;
                ldsm_x4(a0, a1, a2, a3, aA + kk * 32);
                ldsm_x4(b0r, b1r, b2r, b3r, aB + kk * 32);
                mma16816(d0, a0, a1, a2, a3, b0r, b1r);
                mma16816(d1, a0, a1, a2, a3, b2r, b3r);
            }
            {
                int row = r0 + (lane >> 2);
                int col = (lane & 3) * 2;
                red[row * 17 + col]           = d0[0];
                red[row * 17 + col + 1]       = d0[1];
                red[(row + 8) * 17 + col]     = d0[2];
                red[(row + 8) * 17 + col + 1] = d0[3];
                red[row * 17 + col + 8]       = d1[0];
                red[row * 17 + col + 9]       = d1[1];
                red[(row + 8) * 17 + col + 8] = d1[2];
                red[(row + 8) * 17 + col + 9] = d1[3];
            }
            __syncthreads();

            float hval[2];
            {
#pragma unroll
                for (int half = 0; half < 2; half++) {
                    int blh = bl + half * 8;
                    float s0 = bi[0] + red[(jj)      * 17 + blh];
                    float s1 = bi[1] + red[(32 + jj) * 17 + blh];
                    float s2 = bi[2] + red[(64 + jj) * 17 + blh];
                    float s3 = bi[3] + red[(96 + jj) * 17 + blh];
                    c_reg[half] = sigf(s1) * c_reg[half] + sigf(s0) * tanha(s2);
                    hval[half] = sigf(s3) * tanha(c_reg[half]);
                    g_h1buf[tp & (RING - 1)][(size_t)(b0 + blh) * 256 + j0 + jj] =
                        __float2half_rn(hval[half]);
                }
            }
            __syncthreads();
            if (tid == 0) arrive_rel(&g_done1q[tp][bg]);
            // off critical path: archive h1 for the FC
#pragma unroll
            for (int half = 0; half < 2; half++) {
                g_h1all[((size_t)tp * B + b0 + bl + half * 8) * H + j0 + jj] =
                    __float2half_rn(hval[half]);
            }
        }
    }
}

// ------- FC via HMMA: logits = h1 @ fcW^T + fcb ; M=131072, N=64, K=256 -------------
__global__ void __launch_bounds__(256, 2) gemm_fc(const float* __restrict__ fcW,
                                                  const float* __restrict__ fcb) {
    __shared__ __half As[128 * XS];
    __shared__ __half Bs[64 * XS];
    const int tid = threadIdx.x;
    const int warp = tid >> 5, lane = tid & 31;
    const size_t m0 = (size_t)blockIdx.x * 128;

    const int wm = (warp & 3) * 32;
    const int wn = (warp >> 2) * 32;

    float d[2][4][4];
#pragma unroll
    for (int mt = 0; mt < 2; mt++)
#pragma unroll
        for (int nt = 0; nt < 4; nt++)
#pragma unroll
            for (int i = 0; i < 4; i++) d[mt][nt][i] = 0.f;

    const uint32_t sA = smem_u32(As), sB = smem_u32(Bs);
    const uint32_t aA0 = sA + 2u * (uint32_t)((wm + (lane & 15)) * XS + ((lane >> 4) << 3));
    const uint32_t aA1 = aA0 + 2u * 16 * XS;
    const uint32_t aB0 = sB + 2u * (uint32_t)((wn + (lane & 7) + ((lane >> 4) << 3)) * XS
                                              + (((lane >> 3) & 1) << 3));
    const uint32_t aB1 = aB0 + 2u * 16 * XS;

    for (int kc = 0; kc < 4; kc++) {
        for (int i = tid; i < 128 * 8; i += 256) {
            int r = i >> 3, u = i & 7;
            *(uint4*)&As[r * XS + u * 8] =
                *(const uint4*)&g_h1all[(m0 + r) * H + kc * 64 + u * 8];
        }
        for (int i = tid; i < 1024; i += 256) {
            int r = i >> 4, u = i & 15;
            float4 w = *(const float4*)&fcW[(size_t)r * H + kc * 64 + u * 4];
            __half2* dst = (__half2*)&Bs[r * XS + u * 4];
            dst[0] = __floats2half2_rn(w.x, w.y);
            dst[1] = __floats2half2_rn(w.z, w.w);
        }
        __syncthreads();
#pragma unroll
        for (int kk = 0; kk < 4; kk++) {
            uint32_t a0[4], a1[4], b0[4], b1[4];
            ldsm_x4(a0[0], a0[1], a0[2], a0[3], aA0 + kk * 32);
            ldsm_x4(a1[0], a1[1], a1[2], a1[3], aA1 + kk * 32);
            ldsm_x4(b0[0], b0[1], b0[2], b0[3], aB0 + kk * 32);
            ldsm_x4(b1[0], b1[1], b1[2], b1[3], aB1 + kk * 32);
#pragma unroll
            for (int nt = 0; nt < 2; nt++) {
                mma16816(d[0][nt],     a0[0], a0[1], a0[2], a0[3], b0[nt * 2], b0[nt * 2 + 1]);
                mma16816(d[1][nt],     a1[0], a1[1], a1[2], a1[3], b0[nt * 2], b0[nt * 2 + 1]);
                mma16816(d[0][nt + 2], a0[0], a0[1], a0[2], a0[3], b1[nt * 2], b1[nt * 2 + 1]);
                mma16816(d[1][nt + 2], a1[0], a1[1], a1[2], a1[3], b1[nt * 2], b1[nt * 2 + 1]);
            }
        }
        __syncthreads();
    }
    const int rowq = lane >> 2, c2 = (lane & 3) * 2;
#pragma unroll
    for (int mt = 0; mt < 2; mt++) {
#pragma unroll
        for (int nt = 0; nt < 4; nt++) {
            int gc = wn + nt * 8 + c2;
            float bv0 = fcb[gc], bv1 = fcb[gc + 1];
            size_t gr = m0 + wm + mt * 16 + rowq;
            float2 v0 = make_float2(d[mt][nt][0] + bv0, d[mt][nt][1] + bv1);
            float2 v1 = make_float2(d[mt][nt][2] + bv0, d[mt][nt][3] + bv1);
            *(float2*)&g_logits[gr * OUTN + gc]       = v0;
            *(float2*)&g_logits[(gr + 8) * OUTN + gc] = v1;
        }
    }
}

// ---------------- softmax over 64, remap [t][b] -> out[b][t] -----------------------
__global__ void softmax_kernel(float* __restrict__ out) {
    const int tid = threadIdx.x;
    const int lane = tid & 31, w = tid >> 5;
    size_t row = (size_t)blockIdx.x * 8 + w;
    const float* L = g_logits + row * OUTN;
    float v0 = L[lane], v1 = L[lane + 32];
    float mx = fmaxf(v0, v1);
#pragma unroll
    for (int off = 16; off; off >>= 1) mx = fmaxf(mx, __shfl_xor_sync(~0u, mx, off));
    float e0 = expf(v0 - mx), e1 = expf(v1 - mx);
    float s = e0 + e1;
#pragma unroll
    for (int off = 16; off; off >>= 1) s += __shfl_xor_sync(~0u, s, off);
    float inv = 1.f / s;
    int t = (int)(row >> 6), b = (int)(row & 63);
    float* O = out + ((size_t)b * T + t) * OUTN;
    O[lane]      = e0 * inv;
    O[lane + 32] = e1 * inv;
}

// ---------------- launch -------------------------------------------------------------
extern "C" void kernel_launch(void* const* d_in, const int* in_sizes, int n_in,
                              void* d_out, int out_size) {
    const int*   x     = (const int*)d_in[0];
    const float* table = (const float*)d_in[1];
    const float* Wih0  = (const float*)d_in[2];
    const float* Whh0  = (const float*)d_in[3];
    const float* bih0  = (const float*)d_in[4];
    const float* bhh0  = (const float*)d_in[5];
    const float* Wih1  = (const float*)d_in[6];
    const float* Whh1  = (const float*)d_in[7];
    const float* bih1  = (const float*)d_in[8];
    const float* bhh1  = (const float*)d_in[9];
    const float* fcW   = (const float*)d_in[10];
    const float* fcb   = (const float*)d_in[11];
    float* out = (float*)d_out;

    cudaFuncSetAttribute(lstm_kernel,
                         cudaFuncAttributeMaxDynamicSharedMemorySize, SMEM_BYTES);

    void *p0, *p1, *ph0, *ph1;
    cudaGetSymbolAddress(&p0,  g_done0q);
    cudaGetSymbolAddress(&p1,  g_done1q);
    cudaGetSymbolAddress(&ph0, g_h0buf);
    cudaGetSymbolAddress(&ph1, g_h1buf);
    cudaMemsetAsync(p0,  0, T * 4 * sizeof(int));
    cudaMemsetAsync(p1,  0, T * 4 * sizeof(int));
    cudaMemsetAsync(ph0, 0, RING * B * H * sizeof(__half));
    cudaMemsetAsync(ph1, 0, RING * B * H * sizeof(__half));

    prep_bias<<<4, 256>>>(bih0, bhh0, bih1, bhh1);
    embed_kernel<<<(MROWS * D) / 512, 256>>>(x, table);
    gemm_xg0<<<dim3(G4 / 64, MROWS / 128), 256>>>(Wih0);

    lstm_kernel<<<NBLK, 256, SMEM_BYTES>>>(Whh0, Wih1, Whh1);

    gemm_fc<<<MROWS / 128, 256>>>(fcW, fcb);
    softmax_kernel<<<MROWS / 8, 256>>>(out);
}

// round 15
// speedup vs baseline: 1.1670x; 1.1670x over previous
#include <cuda_runtime.h>
#include <cuda_fp16.h>
#include <math.h>
#include <stdint.h>

#define B    64
#define T    2048
#define D    128
#define H    256
#define G4   1024
#define OUTN 64
#define MROWS (T * B)
#define NB_L0 64
#define NB_L1 64
#define NBLK  (NB_L0 + NB_L1)
#define RING 4

typedef unsigned long long ull;

// lstm dynamic SMEM layout (bytes)
#define OFF_B   66560
#define OFF_RED 83200
#define SMEM_BYTES 87552

// ---------------- scratch ------------------------------------------------------
__device__ __half g_eh[(size_t)MROWS * D];          // [m][d] fp16
__device__ float  g_xg0[(size_t)MROWS * G4];        // [m][col] (includes bias0)
__device__ __half g_h1all[(size_t)MROWS * H];       // [m][k] fp16
__device__ float  g_logits[(size_t)MROWS * OUTN];
__device__ __half g_h0buf[RING][B * H];             // [ring][b][k]
__device__ __half g_h1buf[RING][B * H];
__device__ float  g_bias0[G4];
__device__ float  g_bias1[G4];
__device__ int    g_done0q[T][4];                   // 16 block-arrivals each
__device__ int    g_done1q[T][4];

__device__ __forceinline__ float tanha(float x) {
    float r;
    asm("tanh.approx.f32 %0, %1;" : "=f"(r) : "f"(x));
    return r;
}
__device__ __forceinline__ float sigf(float x) { return 0.5f * tanha(0.5f * x) + 0.5f; }

__device__ __forceinline__ void waitq(const int* p, int thr) {
    int v;
    do {
        asm volatile("ld.global.acquire.gpu.b32 %0, [%1];" : "=r"(v) : "l"(p) : "memory");
    } while (v < thr);
}
__device__ __forceinline__ void arrive_rel(int* p) {
    asm volatile("red.release.gpu.global.add.u32 [%0], %1;" :: "l"(p), "r"(1) : "memory");
}

// ---------------- warp MMA helpers -----------------------------------------------
__device__ __forceinline__ uint32_t smem_u32(const void* p) {
    uint32_t a;
    asm("{ .reg .u64 t; cvta.to.shared.u64 t, %1; cvt.u32.u64 %0, t; }" : "=r"(a) : "l"(p));
    return a;
}
__device__ __forceinline__ void ldsm_x4(uint32_t& a0, uint32_t& a1, uint32_t& a2,
                                        uint32_t& a3, uint32_t addr) {
    asm volatile("ldmatrix.sync.aligned.m8n8.x4.shared.b16 {%0,%1,%2,%3}, [%4];"
                 : "=r"(a0), "=r"(a1), "=r"(a2), "=r"(a3) : "r"(addr));
}
__device__ __forceinline__ void ldsm_x2(uint32_t& b0, uint32_t& b1, uint32_t addr) {
    asm volatile("ldmatrix.sync.aligned.m8n8.x2.shared.b16 {%0,%1}, [%2];"
                 : "=r"(b0), "=r"(b1) : "r"(addr));
}
__device__ __forceinline__ void mma16816(float* d, uint32_t a0, uint32_t a1,
                                         uint32_t a2, uint32_t a3,
                                         uint32_t b0, uint32_t b1) {
    asm volatile(
        "mma.sync.aligned.m16n8k16.row.col.f32.f16.f16.f32 "
        "{%0,%1,%2,%3}, {%4,%5,%6,%7}, {%8,%9}, {%0,%1,%2,%3};"
        : "+f"(d[0]), "+f"(d[1]), "+f"(d[2]), "+f"(d[3])
        : "r"(a0), "r"(a1), "r"(a2), "r"(a3), "r"(b0), "r"(b1));
}

// ---------------- tiny kernels -----------------------------------------------------
__global__ void prep_bias(const float* __restrict__ bih0, const float* __restrict__ bhh0,
                          const float* __restrict__ bih1, const float* __restrict__ bhh1) {
    int i = blockIdx.x * 256 + threadIdx.x;
    if (i < G4) {
        g_bias0[i] = bih0[i] + bhh0[i];
        g_bias1[i] = bih1[i] + bhh1[i];
    }
}

__global__ void embed_kernel(const int* __restrict__ x, const float* __restrict__ table) {
    size_t idx = ((size_t)blockIdx.x * 256 + threadIdx.x) * 2;
    int d = (int)(idx & (D - 1));
    size_t m = idx >> 7;
    int t = (int)(m >> 6);
    int b = (int)(m & 63);
    int xi = __ldg(&x[(size_t)b * T + t]);
    __half2 v;
    if (xi == 0) {
        v = __floats2half2_rn(0.f, 0.f);
    } else {
        const float* src = &table[(size_t)xi * D + d];
        v = __floats2half2_rn(src[0], src[1]);
    }
    *(__half2*)&g_eh[idx] = v;
}

// ------- xg0 = e @ Wih0^T + bias0 via HMMA; M=131072, N(gates)=1024, K=128 ---------
#define XS 72
__global__ void __launch_bounds__(256, 2) gemm_xg0(const float* __restrict__ Wih) {
    __shared__ __half As[128 * XS];
    __shared__ __half Bs[64 * XS];
    const int tid = threadIdx.x;
    const int warp = tid >> 5, lane = tid & 31;
    const size_t m0 = (size_t)blockIdx.y * 128;
    const int    n0 = blockIdx.x * 64;

    const int wm = (warp & 3) * 32;
    const int wn = (warp >> 2) * 32;

    float d[2][4][4];
#pragma unroll
    for (int mt = 0; mt < 2; mt++)
#pragma unroll
        for (int nt = 0; nt < 4; nt++)
#pragma unroll
            for (int i = 0; i < 4; i++) d[mt][nt][i] = 0.f;

    const uint32_t sA = smem_u32(As), sB = smem_u32(Bs);
    const uint32_t aA0 = sA + 2u * (uint32_t)((wm + (lane & 15)) * XS + ((lane >> 4) << 3));
    const uint32_t aA1 = aA0 + 2u * 16 * XS;
    const uint32_t aB0 = sB + 2u * (uint32_t)((wn + (lane & 7) + ((lane >> 4) << 3)) * XS
                                              + (((lane >> 3) & 1) << 3));
    const uint32_t aB1 = aB0 + 2u * 16 * XS;

    for (int kc = 0; kc < 2; kc++) {
        for (int i = tid; i < 128 * 8; i += 256) {
            int r = i >> 3, u = i & 7;
            *(uint4*)&As[r * XS + u * 8] =
                *(const uint4*)&g_eh[(m0 + r) * D + kc * 64 + u * 8];
        }
        for (int i = tid; i < 1024; i += 256) {
            int r = i >> 4, u = i & 15;
            float4 w = *(const float4*)&Wih[(size_t)(n0 + r) * D + kc * 64 + u * 4];
            __half2* dst = (__half2*)&Bs[r * XS + u * 4];
            dst[0] = __floats2half2_rn(w.x, w.y);
            dst[1] = __floats2half2_rn(w.z, w.w);
        }
        __syncthreads();
#pragma unroll
        for (int kk = 0; kk < 4; kk++) {
            uint32_t a0[4], a1[4], b0[4], b1[4];
            ldsm_x4(a0[0], a0[1], a0[2], a0[3], aA0 + kk * 32);
            ldsm_x4(a1[0], a1[1], a1[2], a1[3], aA1 + kk * 32);
            ldsm_x4(b0[0], b0[1], b0[2], b0[3], aB0 + kk * 32);
            ldsm_x4(b1[0], b1[1], b1[2], b1[3], aB1 + kk * 32);
#pragma unroll
            for (int nt = 0; nt < 2; nt++) {
                mma16816(d[0][nt],     a0[0], a0[1], a0[2], a0[3], b0[nt * 2], b0[nt * 2 + 1]);
                mma16816(d[1][nt],     a1[0], a1[1], a1[2], a1[3], b0[nt * 2], b0[nt * 2 + 1]);
                mma16816(d[0][nt + 2], a0[0], a0[1], a0[2], a0[3], b1[nt * 2], b1[nt * 2 + 1]);
                mma16816(d[1][nt + 2], a1[0], a1[1], a1[2], a1[3], b1[nt * 2], b1[nt * 2 + 1]);
            }
        }
        __syncthreads();
    }
    const int rowq = lane >> 2, c2 = (lane & 3) * 2;
#pragma unroll
    for (int mt = 0; mt < 2; mt++) {
#pragma unroll
        for (int nt = 0; nt < 4; nt++) {
            int gc = n0 + wn + nt * 8 + c2;
            float bv0 = g_bias0[gc], bv1 = g_bias0[gc + 1];
            size_t gr = m0 + wm + mt * 16 + rowq;
            float2 v0 = make_float2(d[mt][nt][0] + bv0, d[mt][nt][1] + bv1);
            float2 v1 = make_float2(d[mt][nt][2] + bv0, d[mt][nt][3] + bv1);
            *(float2*)&g_xg0[gr * G4 + gc]       = v0;
            *(float2*)&g_xg0[(gr + 8) * G4 + gc] = v1;
        }
    }
}

// ---------------- persistent HMMA 2-layer LSTM (R13 structure) -----------------------
extern __shared__ __align__(1024) char smem_raw[];

__global__ void __launch_bounds__(256, 1) lstm_kernel(
    const float* __restrict__ Whh0,
    const float* __restrict__ Wih1,
    const float* __restrict__ Whh1)
{
    float* red = (float*)(smem_raw + OFF_RED);   // [64][17]
    const uint32_t sbase = smem_u32(smem_raw);
    const int bid = blockIdx.x, tid = threadIdx.x;
    const int warp = tid >> 5, lane = tid & 31;

    const bool isL0 = bid < NB_L0;
    const int lb = isL0 ? bid : bid - NB_L0;
    const int jg = lb >> 2, bg = lb & 3;
    const int j0 = jg * 16, b0 = bg * 16;
    const int K  = isL0 ? 256 : 512;
    const int SA = isL0 ? 264 : 520;

    {
        __half* A_s = (__half*)smem_raw;
        for (int i = tid; i < 64 * K; i += 256) {
            int r = i / K, k = i - r * K;
            int grow = (r >> 4) * 256 + j0 + (r & 15);
            float w;
            if (isL0)          w = Whh0[(size_t)grow * H + k];
            else if (k < 256)  w = Wih1[(size_t)grow * H + k];
            else               w = Whh1[(size_t)grow * H + (k - 256)];
            A_s[r * SA + k] = __float2half_rn(w);
        }
    }

    const int r0 = (warp & 3) * 16, n0w = (warp >> 2) * 8;
    const uint32_t aA = sbase + 2u * (uint32_t)((r0 + (lane & 15)) * SA + ((lane >> 4) << 3));
    const int blane = lane & 15;
    const uint32_t aB = sbase + OFF_B +
        2u * (uint32_t)(((n0w + (blane & 7)) * SA) + (((blane >> 3) & 1) << 3));

    const int jj = tid & 15, bl = tid >> 4;
    float c_reg = 0.f;
    float bi[4];
    if (!isL0) {
#pragma unroll
        for (int g = 0; g < 4; g++) bi[g] = g_bias1[g * 256 + j0 + jj];
    }
    __syncthreads();

    const uint32_t SBb = 2u * (uint32_t)SA;

    if (isL0) {
        // ===================== layer 0 =====================
        for (int t = 0; t < T; ++t) {
            float xp[4];
            {
                const float* xg = g_xg0 + ((size_t)t * B + b0 + bl) * G4 + j0 + jj;
#pragma unroll
                for (int g = 0; g < 4; g++) xp[g] = xg[g * 256];
            }

            // merged poll: both counters in one loop (independent loads)
            if (t >= 1) {
                const int* pa = &g_done0q[t - 1][bg];
                const int* pb = &g_done1q[(t >= RING) ? (t - RING) : 0][bg];
                const bool needb = (t >= RING);
                int va, vb;
                do {
                    asm volatile("ld.global.acquire.gpu.b32 %0, [%1];"
                                 : "=r"(va) : "l"(pa) : "memory");
                    if (needb)
                        asm volatile("ld.global.acquire.gpu.b32 %0, [%1];"
                                     : "=r"(vb) : "l"(pb) : "memory");
                    else vb = 16;
                } while (va < 16 || vb < 16);
            }

            char* smB = smem_raw + OFF_B;
            const __half* hsrc = g_h0buf[(t + RING - 1) & (RING - 1)];
#pragma unroll
            for (int rep = 0; rep < 2; rep++) {
                int c = rep * 256 + tid;
                int n = c >> 5, u = c & 31;
                uint4 v = *(const uint4*)(hsrc + (size_t)(b0 + n) * 256 + u * 8);
                *(uint4*)(smB + n * SBb + u * 16) = v;
            }
            __syncthreads();

            float d[4] = {0.f, 0.f, 0.f, 0.f};
#pragma unroll 8
            for (int kk = 0; kk < 16; kk++) {
                uint32_t a0, a1, a2, a3, bb0, bb1;
                ldsm_x4(a0, a1, a2, a3, aA + kk * 32);
                ldsm_x2(bb0, bb1, aB + kk * 32);
                mma16816(d, a0, a1, a2, a3, bb0, bb1);
            }
            {
                int row = r0 + (lane >> 2);
                int col = n0w + (lane & 3) * 2;
                red[row * 17 + col]           = d[0];
                red[row * 17 + col + 1]       = d[1];
                red[(row + 8) * 17 + col]     = d[2];
                red[(row + 8) * 17 + col + 1] = d[3];
            }
            __syncthreads();

            {
                float s0 = xp[0] + red[(jj)      * 17 + bl];
                float s1 = xp[1] + red[(16 + jj) * 17 + bl];
                float s2 = xp[2] + red[(32 + jj) * 17 + bl];
                float s3 = xp[3] + red[(48 + jj) * 17 + bl];
                c_reg = sigf(s1) * c_reg + sigf(s0) * tanha(s2);
                float hval = sigf(s3) * tanha(c_reg);
                g_h0buf[t & (RING - 1)][(size_t)(b0 + bl) * 256 + j0 + jj] =
                    __float2half_rn(hval);
            }
            __syncthreads();
            if (tid == 0) arrive_rel(&g_done0q[t][bg]);
        }
    } else {
        // ===================== layer 1 (h0 part FIRST, h1 part second) =========
        for (int tp = 0; tp < T; ++tp) {
            char* smB = smem_raw + OFF_B;

            // ---- phase 1: h0(tp) contribution (wait usually non-binding) ----
            waitq(&g_done0q[tp][bg], 16);
            {
                const __half* h0s = g_h0buf[tp & (RING - 1)];
#pragma unroll
                for (int rep = 0; rep < 2; rep++) {
                    int c = rep * 256 + tid;
                    int n = c >> 5, u = c & 31;
                    uint4 v = *(const uint4*)(h0s + (size_t)(b0 + n) * 256 + u * 8);
                    *(uint4*)(smB + n * SBb + u * 16) = v;   // cols 0..255
                }
            }
            __syncthreads();

            float d[4] = {0.f, 0.f, 0.f, 0.f};
#pragma unroll 8
            for (int kk = 0; kk < 16; kk++) {
                uint32_t a0, a1, a2, a3, bb0, bb1;
                ldsm_x4(a0, a1, a2, a3, aA + kk * 32);
                ldsm_x2(bb0, bb1, aB + kk * 32);
                mma16816(d, a0, a1, a2, a3, bb0, bb1);
            }

            // ---- phase 2: h1(tp-1) contribution (the real dependency) ----
            if (tp >= 1) waitq(&g_done1q[tp - 1][bg], 16);
            {
                const __half* h1s = g_h1buf[(tp + RING - 1) & (RING - 1)];
#pragma unroll
                for (int rep = 0; rep < 2; rep++) {
                    int c = rep * 256 + tid;
                    int n = c >> 5, u = c & 31;
                    uint4 v = *(const uint4*)(h1s + (size_t)(b0 + n) * 256 + u * 8);
                    *(uint4*)(smB + n * SBb + 512 + u * 16) = v;   // cols 256..511
                }
            }
            __syncthreads();

#pragma unroll 8
            for (int kk = 16; kk < 32; kk++) {
                uint32_t a0, a1, a2, a3, bb0, bb1;
                ldsm_x4(a0, a1, a2, a3, aA + kk * 32);
                ldsm_x2(bb0, bb1, aB + kk * 32);
                mma16816(d, a0, a1, a2, a3, bb0, bb1);
            }
            {
                int row = r0 + (lane >> 2);
                int col = n0w + (lane & 3) * 2;
                red[row * 17 + col]           = d[0];
                red[row * 17 + col + 1]       = d[1];
                red[(row + 8) * 17 + col]     = d[2];
                red[(row + 8) * 17 + col + 1] = d[3];
            }
            __syncthreads();

            float hval;
            {
                float s0 = bi[0] + red[(jj)      * 17 + bl];
                float s1 = bi[1] + red[(16 + jj) * 17 + bl];
                float s2 = bi[2] + red[(32 + jj) * 17 + bl];
                float s3 = bi[3] + red[(48 + jj) * 17 + bl];
                c_reg = sigf(s1) * c_reg + sigf(s0) * tanha(s2);
                hval = sigf(s3) * tanha(c_reg);
                g_h1buf[tp & (RING - 1)][(size_t)(b0 + bl) * 256 + j0 + jj] =
                    __float2half_rn(hval);
            }
            __syncthreads();
            if (tid == 0) arrive_rel(&g_done1q[tp][bg]);
            // off critical path: archive h1 for the FC (kernel-ordered consumer)
            g_h1all[((size_t)tp * B + b0 + bl) * H + j0 + jj] = __float2half_rn(hval);
        }
    }
}

// ------- FC via HMMA: logits = h1 @ fcW^T + fcb ; M=131072, N=64, K=256 -------------
__global__ void __launch_bounds__(256, 2) gemm_fc(const float* __restrict__ fcW,
                                                  const float* __restrict__ fcb) {
    __shared__ __half As[128 * XS];
    __shared__ __half Bs[64 * XS];
    const int tid = threadIdx.x;
    const int warp = tid >> 5, lane = tid & 31;
    const size_t m0 = (size_t)blockIdx.x * 128;

    const int wm = (warp & 3) * 32;
    const int wn = (warp >> 2) * 32;

    float d[2][4][4];
#pragma unroll
    for (int mt = 0; mt < 2; mt++)
#pragma unroll
        for (int nt = 0; nt < 4; nt++)
#pragma unroll
            for (int i = 0; i < 4; i++) d[mt][nt][i] = 0.f;

    const uint32_t sA = smem_u32(As), sB = smem_u32(Bs);
    const uint32_t aA0 = sA + 2u * (uint32_t)((wm + (lane & 15)) * XS + ((lane >> 4) << 3));
    const uint32_t aA1 = aA0 + 2u * 16 * XS;
    const uint32_t aB0 = sB + 2u * (uint32_t)((wn + (lane & 7) + ((lane >> 4) << 3)) * XS
                                              + (((lane >> 3) & 1) << 3));
    const uint32_t aB1 = aB0 + 2u * 16 * XS;

    for (int kc = 0; kc < 4; kc++) {
        for (int i = tid; i < 128 * 8; i += 256) {
            int r = i >> 3, u = i & 7;
            *(uint4*)&As[r * XS + u * 8] =
                *(const uint4*)&g_h1all[(m0 + r) * H + kc * 64 + u * 8];
        }
        for (int i = tid; i < 1024; i += 256) {
            int r = i >> 4, u = i & 15;
            float4 w = *(const float4*)&fcW[(size_t)r * H + kc * 64 + u * 4];
            __half2* dst = (__half2*)&Bs[r * XS + u * 4];
            dst[0] = __floats2half2_rn(w.x, w.y);
            dst[1] = __floats2half2_rn(w.z, w.w);
        }
        __syncthreads();
#pragma unroll
        for (int kk = 0; kk < 4; kk++) {
            uint32_t a0[4], a1[4], b0[4], b1[4];
            ldsm_x4(a0[0], a0[1], a0[2], a0[3], aA0 + kk * 32);
            ldsm_x4(a1[0], a1[1], a1[2], a1[3], aA1 + kk * 32);
            ldsm_x4(b0[0], b0[1], b0[2], b0[3], aB0 + kk * 32);
            ldsm_x4(b1[0], b1[1], b1[2], b1[3], aB1 + kk * 32);
#pragma unroll
            for (int nt = 0; nt < 2; nt++) {
                mma16816(d[0][nt],     a0[0], a0[1], a0[2], a0[3], b0[nt * 2], b0[nt * 2 + 1]);
                mma16816(d[1][nt],     a1[0], a1[1], a1[2], a1[3], b0[nt * 2], b0[nt * 2 + 1]);
                mma16816(d[0][nt + 2], a0[0], a0[1], a0[2], a0[3], b1[nt * 2], b1[nt * 2 + 1]);
                mma16816(d[1][nt + 2], a1[0], a1[1], a1[2], a1[3], b1[nt * 2], b1[nt * 2 + 1]);
            }
        }
        __syncthreads();
    }
    const int rowq = lane >> 2, c2 = (lane & 3) * 2;
#pragma unroll
    for (int mt = 0; mt < 2; mt++) {
#pragma unroll
        for (int nt = 0; nt < 4; nt++) {
            int gc = wn + nt * 8 + c2;
            float bv0 = fcb[gc], bv1 = fcb[gc + 1];
            size_t gr = m0 + wm + mt * 16 + rowq;
            float2 v0 = make_float2(d[mt][nt][0] + bv0, d[mt][nt][1] + bv1);
            float2 v1 = make_float2(d[mt][nt][2] + bv0, d[mt][nt][3] + bv1);
            *(float2*)&g_logits[gr * OUTN + gc]       = v0;
            *(float2*)&g_logits[(gr + 8) * OUTN + gc] = v1;
        }
    }
}

// ---------------- softmax over 64, remap [t][b] -> out[b][t] -----------------------
__global__ void softmax_kernel(float* __restrict__ out) {
    const int tid = threadIdx.x;
    const int lane = tid & 31, w = tid >> 5;
    size_t row = (size_t)blockIdx.x * 8 + w;
    const float* L = g_logits + row * OUTN;
    float v0 = L[lane], v1 = L[lane + 32];
    float mx = fmaxf(v0, v1);
#pragma unroll
    for (int off = 16; off; off >>= 1) mx = fmaxf(mx, __shfl_xor_sync(~0u, mx, off));
    float e0 = expf(v0 - mx), e1 = expf(v1 - mx);
    float s = e0 + e1;
#pragma unroll
    for (int off = 16; off; off >>= 1) s += __shfl_xor_sync(~0u, s, off);
    float inv = 1.f / s;
    int t = (int)(row >> 6), b = (int)(row & 63);
    float* O = out + ((size_t)b * T + t) * OUTN;
    O[lane]      = e0 * inv;
    O[lane + 32] = e1 * inv;
}

// ---------------- launch -------------------------------------------------------------
extern "C" void kernel_launch(void* const* d_in, const int* in_sizes, int n_in,
                              void* d_out, int out_size) {
    const int*   x     = (const int*)d_in[0];
    const float* table = (const float*)d_in[1];
    const float* Wih0  = (const float*)d_in[2];
    const float* Whh0  = (const float*)d_in[3];
    const float* bih0  = (const float*)d_in[4];
    const float* bhh0  = (const float*)d_in[5];
    const float* Wih1  = (const float*)d_in[6];
    const float* Whh1  = (const float*)d_in[7];
    const float* bih1  = (const float*)d_in[8];
    const float* bhh1  = (const float*)d_in[9];
    const float* fcW   = (const float*)d_in[10];
    const float* fcb   = (const float*)d_in[11];
    float* out = (float*)d_out;

    cudaFuncSetAttribute(lstm_kernel,
                         cudaFuncAttributeMaxDynamicSharedMemorySize, SMEM_BYTES);

    void *p0, *p1, *ph0, *ph1;
    cudaGetSymbolAddress(&p0,  g_done0q);
    cudaGetSymbolAddress(&p1,  g_done1q);
    cudaGetSymbolAddress(&ph0, g_h0buf);
    cudaGetSymbolAddress(&ph1, g_h1buf);
    cudaMemsetAsync(p0,  0, T * 4 * sizeof(int));
    cudaMemsetAsync(p1,  0, T * 4 * sizeof(int));
    cudaMemsetAsync(ph0, 0, RING * B * H * sizeof(__half));
    cudaMemsetAsync(ph1, 0, RING * B * H * sizeof(__half));

    prep_bias<<<4, 256>>>(bih0, bhh0, bih1, bhh1);
    embed_kernel<<<(MROWS * D) / 512, 256>>>(x, table);
    gemm_xg0<<<dim3(G4 / 64, MROWS / 128), 256>>>(Wih0);

    lstm_kernel<<<NBLK, 256, SMEM_BYTES>>>(Whh0, Wih1, Whh1);

    gemm_fc<<<MROWS / 128, 256>>>(fcW, fcb);
    softmax_kernel<<<MROWS / 8, 256>>>(out);
}